// round 7
// baseline (speedup 1.0000x reference)
#include <cuda_runtime.h>
#include <cstdint>

#define BS      16
#define CIN     32
#define COUT    64
#define OUT_DIM 1024
#define P_BLK   2
#define THREADS 128                 // pp(2) x bg(8) x og(8)
#define NBLOCKS (OUT_DIM / P_BLK)   // 512

// smem x tile, float4 granules: per c, 32 granules (pp:2 x b:16); granule =
// one batch's k-quad for one patch. Logical (pp,b) at phys H = pp*16 + (b^pp)
// => every 8-lane LDS.128 phase hits 8 distinct 16B chunks (conflict-free).
#define CSTRIDE4 33                 // 32 granules + 1 pad (528 B per c)
#define SMEM_F4  (CIN * CSTRIDE4)   // 16.9 KB

typedef unsigned long long ull;

__global__ __launch_bounds__(THREADS, 4)
void lc1d_v4(const float* __restrict__ x,
             const float* __restrict__ w,
             float* __restrict__ out)
{
    __shared__ __align__(16) float4 xs4[SMEM_F4];

    const int tid = threadIdx.x;
    const int blk = blockIdx.x;

    // ---------------- producer: stage x tile (8 float4 per thread) ----------
    {
        const float4* x4 = reinterpret_cast<const float4*>(x);
        #pragma unroll
        for (int it = 0; it < 8; ++it) {
            int i  = it * THREADS + tid;     // 0..1023
            int pp = i & 1;
            int c  = (i >> 1) & 31;
            int b  = i >> 6;                 // 0..15
            float4 v = x4[(size_t)(b * CIN + c) * OUT_DIM + (size_t)blk * P_BLK + pp];
            xs4[c * CSTRIDE4 + pp * 16 + (b ^ pp)] = v;
        }
    }
    __syncthreads();

    // ---------------- consumer: thread = 8 o  x  2 b  x  1 p ----------------
    const int pp = tid & 1;
    const int bg = (tid >> 1) & 7;     // batches 2*bg, 2*bg+1
    const int og = tid >> 4;           // o = 8*og + i
    const int p  = blk * P_BLK + pp;

    uint32_t sbase;
    asm("{ .reg .u64 t; cvta.to.shared.u64 t, %1; cvt.u32.u64 %0, t; }"
        : "=r"(sbase) : "l"(xs4));

    uint32_t a0 = sbase + 16u * (uint32_t)(pp * 16 + ((2 * bg)     ^ pp));
    uint32_t a1 = sbase + 16u * (uint32_t)(pp * 16 + ((2 * bg + 1) ^ pp));

    // acc[i*2+q]: o = 8*og+i, b = 2*bg+q; f32x2 lanes hold (k02, k13) partials
    ull acc[16];
    #pragma unroll
    for (int t = 0; t < 16; ++t) acc[t] = 0ULL;

    // w as 16B k-quads: index = (o*CIN + c)*1024 + p
    const ulonglong2* wp = reinterpret_cast<const ulonglong2*>(w)
                         + (size_t)(og * 8) * (CIN * 1024) + (size_t)blk * P_BLK + pp;

    // double-buffered w: 8 o's x {lo=(k0,k1), hi=(k2,k3)}
    ull wlo[2][8], whi[2][8];
    #pragma unroll
    for (int i = 0; i < 8; ++i) {
        ulonglong2 t = wp[(size_t)i * (CIN * 1024)];
        wlo[0][i] = t.x; whi[0][i] = t.y;
    }

    #pragma unroll 2
    for (int c = 0; c < CIN; ++c) {
        const int cur = c & 1, nxt = cur ^ 1;
        // front-batched prefetch of next c (8 independent LDGs, MLP_p1 = 8)
        if (c + 1 < CIN) {
            const ulonglong2* wn = wp + (size_t)(c + 1) * 1024;
            #pragma unroll
            for (int i = 0; i < 8; ++i) {
                ulonglong2 t = wn[(size_t)i * (CIN * 1024)];
                wlo[nxt][i] = t.x; whi[nxt][i] = t.y;
            }
        }

        // x for the 2 owned batches
        ull xlo0, xhi0, xlo1, xhi1;
        asm("ld.shared.v2.u64 {%0, %1}, [%2];" : "=l"(xlo0), "=l"(xhi0) : "r"(a0));
        asm("ld.shared.v2.u64 {%0, %1}, [%2];" : "=l"(xlo1), "=l"(xhi1) : "r"(a1));
        a0 += CSTRIDE4 * 16; a1 += CSTRIDE4 * 16;

        #pragma unroll
        for (int i = 0; i < 8; ++i) {
            const ull wl = wlo[cur][i], wh = whi[cur][i];
            asm("fma.rn.f32x2 %0, %1, %2, %0;" : "+l"(acc[i * 2 + 0]) : "l"(xlo0), "l"(wl));
            asm("fma.rn.f32x2 %0, %1, %2, %0;" : "+l"(acc[i * 2 + 0]) : "l"(xhi0), "l"(wh));
            asm("fma.rn.f32x2 %0, %1, %2, %0;" : "+l"(acc[i * 2 + 1]) : "l"(xlo1), "l"(wl));
            asm("fma.rn.f32x2 %0, %1, %2, %0;" : "+l"(acc[i * 2 + 1]) : "l"(xhi1), "l"(wh));
        }
    }

    // ---------------- epilogue: fold k-lanes, scale, store ----------------
    const float sc = 0.17677669529663687f;   // 1/sqrt(32)
    #pragma unroll
    for (int i = 0; i < 8; ++i) {
        const int o = og * 8 + i;
        #pragma unroll
        for (int q = 0; q < 2; ++q) {
            float lo, hi;
            asm("mov.b64 {%0, %1}, %2;" : "=f"(lo), "=f"(hi) : "l"(acc[i * 2 + q]));
            const int b = bg * 2 + q;
            out[(size_t)b * (COUT * OUT_DIM) + (size_t)o * OUT_DIM + p] = (lo + hi) * sc;
        }
    }
}

extern "C" void kernel_launch(void* const* d_in, const int* in_sizes, int n_in,
                              void* d_out, int out_size)
{
    const float* x = (const float*)d_in[0];   // [16, 32, 4096]
    const float* w = (const float*)d_in[1];   // [64, 32, 4096]
    float* out = (float*)d_out;               // [16, 64, 1024]
    (void)in_sizes; (void)n_in; (void)out_size;

    lc1d_v4<<<NBLOCKS, THREADS>>>(x, w, out);
}